// round 7
// baseline (speedup 1.0000x reference)
#include <cuda_runtime.h>

#define BB 8
#define T 32768
#define R 64
#define S 128
#define NBLK 24
#define TT 128
#define AST 136   // smem activation row stride; 136 mod 32 == 8 -> B-frag LDS conflict-free

typedef unsigned int u32;

__device__ __align__(16) float g_h[2][BB * R * T];   // ping-pong fp32 residual stream
__device__ __align__(16) float g_skip[BB * S * T];   // fp32 skip accumulator

// Fragment-ordered tf32 weights, hi + lo split (built once per launch by prep_kernel).
#define P1N 8192
#define P2N 8192
#define P3N 12288
__device__ __align__(16) float g_p1h[NBLK * P1N], g_p1l[NBLK * P1N];
__device__ __align__(16) float g_p2h[NBLK * P2N], g_p2l[NBLK * P2N];
__device__ __align__(16) float g_p3h[NBLK * P3N], g_p3l[NBLK * P3N];

__device__ __forceinline__ float tf32r(float x) {
    u32 o; asm("cvt.rna.tf32.f32 %0, %1;" : "=r"(o) : "f"(x));
    return __uint_as_float(o);
}
// Low 13 mantissa bits (the part tf32 hardware truncation discards)
__device__ __forceinline__ float lo_part(float x) {
    return x - __uint_as_float(__float_as_uint(x) & 0xFFFFE000u);
}
__device__ __forceinline__ float sigf(float x) { return 1.f / (1.f + expf(-x)); }

#define MMA(d, a, b0, b1) \
    asm("mma.sync.aligned.m16n8k8.row.col.f32.tf32.tf32.f32 " \
        "{%0,%1,%2,%3}, {%4,%5,%6,%7}, {%8,%9}, {%0,%1,%2,%3};" \
        : "+f"(d[0]), "+f"(d[1]), "+f"(d[2]), "+f"(d[3]) \
        : "r"(a.x), "r"(a.y), "r"(a.z), "r"(a.w), "r"(b0), "r"(b1))

// 3-MMA full-precision tile update: D += W * b with W = Ah+Al (prebaked tf32 pair),
// b fp32 (HW truncates to hi), bl = discarded low bits.
#define MMA3(d, Ah, Al, bv0, bv1) do {                         \
    u32 _b0 = __float_as_uint(bv0), _b1 = __float_as_uint(bv1);\
    u32 _l0 = __float_as_uint(lo_part(bv0));                   \
    u32 _l1 = __float_as_uint(lo_part(bv1));                   \
    MMA(d, Ah, _b0, _b1);                                      \
    MMA(d, Al, _b0, _b1);                                      \
    MMA(d, Ah, _l0, _l1);                                      \
} while (0)

__device__ __forceinline__ void fma4(float4 &a, float w, const float4 &v) {
    a.x = fmaf(w, v.x, a.x); a.y = fmaf(w, v.y, a.y);
    a.z = fmaf(w, v.z, a.z); a.w = fmaf(w, v.w, a.w);
}

// ---------------------------------------------------------------------------
// Prep: build fragment-ordered hi/lo tf32 weights
// ---------------------------------------------------------------------------
__global__ void prep_kernel(const float* __restrict__ wc, const float* __restrict__ wf,
                            const float* __restrict__ wg, const float* __restrict__ wr,
                            const float* __restrict__ ws) {
    int idx = blockIdx.x * blockDim.x + threadIdx.x;
    const int PER = P1N + P2N + P3N;
    if (idx >= NBLK * PER) return;
    int lyr = idx / PER;
    int e = idx % PER;
    float w; float *dh, *dl;
    if (e < P1N) {
        int slab = e >> 11, kt = (e >> 7) & 15, lane = (e >> 2) & 31, r = e & 3;
        int row = slab * 16 + (lane >> 2) + 8 * (r & 1);
        int k = kt * 8 + (lane & 3) + 4 * (r >> 1);
        w = (k < 64) ? wc[(((size_t)lyr * 64 + row) * 64 + k) * 2]
                     : wc[(((size_t)lyr * 64 + row) * 64 + (k - 64)) * 2 + 1];
        dh = g_p1h + (size_t)lyr * P1N + e;
        dl = g_p1l + (size_t)lyr * P1N + e;
    } else if (e < P1N + P2N) {
        int e2 = e - P1N;
        int slab = e2 >> 10, kt = (e2 >> 7) & 7, lane = (e2 >> 2) & 31, r = e2 & 3;
        int ch = slab * 8 + (lane >> 2);
        int k = kt * 8 + (lane & 3) + 4 * (r >> 1);
        w = ((r & 1) == 0) ? wf[((size_t)lyr * 64 + ch) * 64 + k]
                           : wg[((size_t)lyr * 64 + ch) * 64 + k];
        dh = g_p2h + (size_t)lyr * P2N + e2;
        dl = g_p2l + (size_t)lyr * P2N + e2;
    } else {
        int e3 = e - P1N - P2N;
        int slab = e3 >> 10, kt = (e3 >> 7) & 7, lane = (e3 >> 2) & 31, r = e3 & 3;
        int cp = slab * 16 + (lane >> 2) + 8 * (r & 1);
        int k = kt * 8 + (lane & 3) + 4 * (r >> 1);
        w = (cp < 64) ? wr[((size_t)lyr * 64 + cp) * 64 + k]
                      : ws[((size_t)lyr * 128 + (cp - 64)) * 64 + k];
        dh = g_p3h + (size_t)lyr * P3N + e3;
        dl = g_p3l + (size_t)lyr * P3N + e3;
    }
    float hi = tf32r(w);
    *dh = hi;
    *dl = tf32r(w - hi);
}

// ---------------------------------------------------------------------------
// Kernel 1: input 1x1 conv
// ---------------------------------------------------------------------------
__global__ void input_kernel(const float* __restrict__ x,
                             const float* __restrict__ w_in,
                             const float* __restrict__ b_in) {
    int idx = blockIdx.x * blockDim.x + threadIdx.x;
    int t = idx & (T - 1);
    int r = (idx >> 15) & (R - 1);
    int b = idx >> 21;
    g_h[0][idx] = fmaf(__ldg(&w_in[r]), __ldg(&x[b * T + t]), __ldg(&b_in[r]));
}

// ---------------------------------------------------------------------------
// Kernel 2: fused WaveNet block on tensor cores (tf32 3-MMA, fp32 activations)
// ---------------------------------------------------------------------------
__global__ void __launch_bounds__(256, 2) block_kernel(
    const float* __restrict__ h_in, float* __restrict__ h_out,
    const uint4* __restrict__ p1h, const uint4* __restrict__ p1l, const float* __restrict__ bc,
    const uint4* __restrict__ p2h, const uint4* __restrict__ p2l, const float* __restrict__ bf,
    const float* __restrict__ bg,
    const uint4* __restrict__ p3h, const uint4* __restrict__ p3l, const float* __restrict__ br,
    const float* __restrict__ bs,
    int d, int first)
{
    extern __shared__ float sm[];
    float* s_hn = sm;                 // [64][AST] fp32 h(t)
    float* s_hp = sm + 64 * AST;      // [64][AST] fp32 h(t-d); reused as a
    float* s_z  = sm + 2 * 64 * AST;  // [64][AST] fp32 z

    const int b = blockIdx.y, t0 = blockIdx.x * TT;
    const int tid = threadIdx.x, wp = tid >> 5, l = tid & 31;
    const int lk = l & 3, ln = l >> 2;       // B-frag k row / n col within tile
    const float* hbase = h_in + (size_t)b * R * T;

    // ---- Phase 0: load activation tiles (exact fp32) ----
    for (int f = tid; f < R * 32; f += 256) {
        int row = f >> 5, c4 = f & 31;
        float4 v = ((const float4*)(hbase + (size_t)row * T + t0))[c4];
        *(float4*)(s_hn + row * AST + c4 * 4) = v;
    }
    if ((d & 3) == 0) {
        const int dq = d >> 2;
        for (int f = tid; f < R * 32; f += 256) {
            int row = f >> 5, c4 = f & 31;
            int tq = (t0 >> 2) + c4 - dq;
            float4 v = (tq >= 0) ? ((const float4*)(hbase + (size_t)row * T))[tq]
                                 : make_float4(0.f, 0.f, 0.f, 0.f);
            *(float4*)(s_hp + row * AST + c4 * 4) = v;
        }
    } else {
        for (int idx = tid; idx < R * TT; idx += 256) {
            int row = idx >> 7, col = idx & 127;
            int t = t0 + col - d;
            s_hp[row * AST + col] = (t >= 0) ? hbase[(size_t)row * T + t] : 0.f;
        }
    }
    __syncthreads();

    // ---- Phase 1: z = Wc x [hp; hn]  (M=64, K=128) ----
    {
        const int slab = wp >> 1, nb = (wp & 1) * 64;
        float acc[8][4];
        #pragma unroll
        for (int nt = 0; nt < 8; nt++)
            acc[nt][0] = acc[nt][1] = acc[nt][2] = acc[nt][3] = 0.f;
        #pragma unroll 4
        for (int kt = 0; kt < 16; kt++) {
            uint4 Ah = __ldg(&p1h[(slab * 16 + kt) * 32 + l]);
            uint4 Al = __ldg(&p1l[(slab * 16 + kt) * 32 + l]);
            const float* bp = ((kt < 8) ? s_hp + kt * 8 * AST
                                        : s_hn + (kt - 8) * 8 * AST) + lk * AST + ln + nb;
            #pragma unroll
            for (int nt = 0; nt < 8; nt++) {
                float bv0 = bp[nt * 8];
                float bv1 = bp[4 * AST + nt * 8];
                MMA3(acc[nt], Ah, Al, bv0, bv1);
            }
        }
        int r0 = slab * 16 + ln;
        float bv0 = __ldg(bc + r0), bv1 = __ldg(bc + r0 + 8);
        #pragma unroll
        for (int nt = 0; nt < 8; nt++) {
            int c0 = nb + nt * 8 + 2 * lk;
            float2 v0 = { acc[nt][0] + bv0, acc[nt][1] + bv0 };
            float2 v1 = { acc[nt][2] + bv1, acc[nt][3] + bv1 };
            *(float2*)(s_z + r0 * AST + c0) = v0;
            *(float2*)(s_z + (r0 + 8) * AST + c0) = v1;
        }
    }
    __syncthreads();

    // ---- Phase 2: a = tanh(Wf z + bf) * sigmoid(Wg z + bg)  (M=128, K=64) ----
    #pragma unroll
    for (int ui = 0; ui < 2; ui++) {
        int u = wp + ui * 8;
        int slab = u >> 1, nb = (u & 1) * 64;
        float acc[8][4];
        #pragma unroll
        for (int nt = 0; nt < 8; nt++)
            acc[nt][0] = acc[nt][1] = acc[nt][2] = acc[nt][3] = 0.f;
        #pragma unroll 2
        for (int kt = 0; kt < 8; kt++) {
            uint4 Ah = __ldg(&p2h[(slab * 8 + kt) * 32 + l]);
            uint4 Al = __ldg(&p2l[(slab * 8 + kt) * 32 + l]);
            const float* bp = s_z + (kt * 8 + lk) * AST + ln + nb;
            #pragma unroll
            for (int nt = 0; nt < 8; nt++) {
                float bv0 = bp[nt * 8];
                float bv1 = bp[4 * AST + nt * 8];
                MMA3(acc[nt], Ah, Al, bv0, bv1);
            }
        }
        int ch = slab * 8 + ln;
        float bfv = __ldg(bf + ch), bgv = __ldg(bg + ch);
        #pragma unroll
        for (int nt = 0; nt < 8; nt++) {
            int c0 = nb + nt * 8 + 2 * lk;
            float a0 = tanhf(acc[nt][0] + bfv) * sigf(acc[nt][2] + bgv);
            float a1 = tanhf(acc[nt][1] + bfv) * sigf(acc[nt][3] + bgv);
            float2 v = { a0, a1 };
            *(float2*)(s_hp + ch * AST + c0) = v;   // a overwrites hp
        }
    }
    __syncthreads();

    // ---- Phase 3: res (rows 0-63) + skip (rows 64-191)  (M=192, K=64) ----
    {
        float* hdst = h_out + (size_t)b * R * T + t0;
        const float* hsrc = h_in + (size_t)b * R * T + t0;
        float* skp = g_skip + (size_t)b * S * T + t0;
        #pragma unroll
        for (int ui = 0; ui < 3; ui++) {
            int u = wp + ui * 8;
            int slab = u >> 1, nb = (u & 1) * 64;
            float acc[8][4];
            #pragma unroll
            for (int nt = 0; nt < 8; nt++)
                acc[nt][0] = acc[nt][1] = acc[nt][2] = acc[nt][3] = 0.f;
            #pragma unroll 2
            for (int kt = 0; kt < 8; kt++) {
                uint4 Ah = __ldg(&p3h[(slab * 8 + kt) * 32 + l]);
                uint4 Al = __ldg(&p3l[(slab * 8 + kt) * 32 + l]);
                const float* bp = s_hp + (kt * 8 + lk) * AST + ln + nb;
                #pragma unroll
                for (int nt = 0; nt < 8; nt++) {
                    float bv0 = bp[nt * 8];
                    float bv1 = bp[4 * AST + nt * 8];
                    MMA3(acc[nt], Ah, Al, bv0, bv1);
                }
            }
            int r0 = slab * 16 + ln;
            if (r0 < 64) {
                float br0 = __ldg(br + r0), br1 = __ldg(br + r0 + 8);
                #pragma unroll
                for (int nt = 0; nt < 8; nt++) {
                    int c0 = nb + nt * 8 + 2 * lk;
                    float2 h0 = *(const float2*)(hsrc + (size_t)r0 * T + c0);
                    float2 h1 = *(const float2*)(hsrc + (size_t)(r0 + 8) * T + c0);
                    float2 v0 = { acc[nt][0] + br0 + h0.x, acc[nt][1] + br0 + h0.y };
                    float2 v1 = { acc[nt][2] + br1 + h1.x, acc[nt][3] + br1 + h1.y };
                    *(float2*)(hdst + (size_t)r0 * T + c0) = v0;
                    *(float2*)(hdst + (size_t)(r0 + 8) * T + c0) = v1;
                }
            } else {
                int s0 = r0 - 64;
                float bs0 = __ldg(bs + s0), bs1 = __ldg(bs + s0 + 8);
                #pragma unroll
                for (int nt = 0; nt < 8; nt++) {
                    int c0 = nb + nt * 8 + 2 * lk;
                    float2* g0 = (float2*)(skp + (size_t)s0 * T + c0);
                    float2* g1 = (float2*)(skp + (size_t)(s0 + 8) * T + c0);
                    float2 v0 = { acc[nt][0] + bs0, acc[nt][1] + bs0 };
                    float2 v1 = { acc[nt][2] + bs1, acc[nt][3] + bs1 };
                    if (!first) {
                        float2 o0 = *g0, o1 = *g1;
                        v0.x += o0.x; v0.y += o0.y; v1.x += o1.x; v1.y += o1.y;
                    }
                    *g0 = v0; *g1 = v1;
                }
            }
        }
    }
}

// ---------------------------------------------------------------------------
// Kernel 3: head (fp32)
// ---------------------------------------------------------------------------
__global__ void __launch_bounds__(256) head_kernel(
    const float* __restrict__ w1, const float* __restrict__ b1,
    const float* __restrict__ w2, const float* __restrict__ b2,
    float* __restrict__ out)
{
    extern __shared__ float smem[];
    float* sk   = smem;
    float* part = smem + S * TT;

    const int b = blockIdx.y, t0 = blockIdx.x * TT;
    const int tid = threadIdx.x, wp = tid >> 5, l = tid & 31;
    const float* skg = g_skip + (size_t)b * S * T + t0;

    for (int f = tid; f < S * TT / 4; f += 256) {
        int row = f >> 5, col = f & 31;
        float4 v = ((const float4*)(skg + (size_t)row * T))[col];
        v.x = fmaxf(v.x, 0.f); v.y = fmaxf(v.y, 0.f);
        v.z = fmaxf(v.z, 0.f); v.w = fmaxf(v.w, 0.f);
        ((float4*)sk)[f] = v;
    }
    __syncthreads();

    const float4* sk4 = (const float4*)sk;
    float4 po = {0.f, 0.f, 0.f, 0.f};
    for (int s2 = wp * 16; s2 < wp * 16 + 16; s2++) {
        float4 u = {0.f, 0.f, 0.f, 0.f};
        const float* wrow = w1 + (s2 << 7);
        #pragma unroll 8
        for (int s1 = 0; s1 < S; s1++)
            fma4(u, __ldg(wrow + s1), sk4[(s1 << 5) + l]);
        float bb = __ldg(b1 + s2);
        u.x = fmaxf(u.x + bb, 0.f); u.y = fmaxf(u.y + bb, 0.f);
        u.z = fmaxf(u.z + bb, 0.f); u.w = fmaxf(u.w + bb, 0.f);
        fma4(po, __ldg(w2 + s2), u);
    }
    ((float4*)(part + wp * TT))[l] = po;
    __syncthreads();

    if (tid < TT) {
        float acc = __ldg(b2);
        #pragma unroll
        for (int ww = 0; ww < 8; ww++) acc += part[ww * TT + tid];
        out[(size_t)b * T + t0 + tid] = acc;
    }
}

// ---------------------------------------------------------------------------
extern "C" void kernel_launch(void* const* d_in, const int* in_sizes, int n_in,
                              void* d_out, int out_size) {
    const float* x        = (const float*)d_in[0];
    const float* w_in     = (const float*)d_in[1];
    const float* b_in     = (const float*)d_in[2];
    const float* w_causal = (const float*)d_in[3];
    const float* b_causal = (const float*)d_in[4];
    const float* w_filter = (const float*)d_in[5];
    const float* b_filter = (const float*)d_in[6];
    const float* w_gate   = (const float*)d_in[7];
    const float* b_gate   = (const float*)d_in[8];
    const float* w_res    = (const float*)d_in[9];
    const float* b_res    = (const float*)d_in[10];
    const float* w_skip   = (const float*)d_in[11];
    const float* b_skip   = (const float*)d_in[12];
    const float* w_out1   = (const float*)d_in[13];
    const float* b_out1   = (const float*)d_in[14];
    const float* w_out2   = (const float*)d_in[15];
    const float* b_out2   = (const float*)d_in[16];
    float* out = (float*)d_out;

    const int blk_smem  = 3 * 64 * AST * 4;          // ~102 KB
    const int head_smem = (S * TT + 8 * TT) * 4;     // 68 KB
    cudaFuncSetAttribute(block_kernel, cudaFuncAttributeMaxDynamicSharedMemorySize, blk_smem);
    cudaFuncSetAttribute(head_kernel,  cudaFuncAttributeMaxDynamicSharedMemorySize, head_smem);

    float *hbuf0, *p1h, *p1l, *p2h, *p2l, *p3h, *p3l;
    cudaGetSymbolAddress((void**)&hbuf0, g_h);
    cudaGetSymbolAddress((void**)&p1h, g_p1h);
    cudaGetSymbolAddress((void**)&p1l, g_p1l);
    cudaGetSymbolAddress((void**)&p2h, g_p2h);
    cudaGetSymbolAddress((void**)&p2l, g_p2l);
    cudaGetSymbolAddress((void**)&p3h, g_p3h);
    cudaGetSymbolAddress((void**)&p3l, g_p3l);
    float* hbuf[2] = { hbuf0, hbuf0 + (size_t)BB * R * T };

    const int pre_total = NBLK * (P1N + P2N + P3N);
    prep_kernel<<<(pre_total + 255) / 256, 256>>>(w_causal, w_filter, w_gate, w_res, w_skip);

    input_kernel<<<BB * R * T / 256, 256>>>(x, w_in, b_in);

    dim3 grid(T / TT, BB);
    for (int i = 0; i < NBLK; i++) {
        int d = 1 << (i & 7);
        block_kernel<<<grid, 256, blk_smem>>>(
            hbuf[i & 1], hbuf[(i + 1) & 1],
            (const uint4*)(p1h + (size_t)i * P1N), (const uint4*)(p1l + (size_t)i * P1N),
            b_causal + (size_t)i * R,
            (const uint4*)(p2h + (size_t)i * P2N), (const uint4*)(p2l + (size_t)i * P2N),
            b_filter + (size_t)i * R, b_gate + (size_t)i * R,
            (const uint4*)(p3h + (size_t)i * P3N), (const uint4*)(p3l + (size_t)i * P3N),
            b_res + (size_t)i * R, b_skip + (size_t)i * S,
            d, i == 0 ? 1 : 0);
    }

    head_kernel<<<grid, 256, head_smem>>>(w_out1, b_out1, w_out2, b_out2, out);
}

// round 8
// speedup vs baseline: 1.0101x; 1.0101x over previous
#include <cuda_runtime.h>

#define BB 8
#define T 32768
#define R 64
#define S 128
#define NBLK 24
#define TT 128
#define AST 136   // smem activation row stride; 136 mod 32 == 8 -> B-frag LDS conflict-free

typedef unsigned int u32;

__device__ __align__(16) float g_h[2][BB * R * T];   // ping-pong fp32 residual stream
__device__ __align__(16) float g_skip[BB * S * T];   // fp32 skip accumulator

// Fragment-ordered tf32 weights, hi + lo split (built once per launch by prep_kernel).
#define P1N 8192
#define P2N 8192
#define P3N 12288
__device__ __align__(16) float g_p1h[NBLK * P1N], g_p1l[NBLK * P1N];
__device__ __align__(16) float g_p2h[NBLK * P2N], g_p2l[NBLK * P2N];
__device__ __align__(16) float g_p3h[NBLK * P3N], g_p3l[NBLK * P3N];

__device__ __forceinline__ float tf32r(float x) {
    u32 o; asm("cvt.rna.tf32.f32 %0, %1;" : "=r"(o) : "f"(x));
    return __uint_as_float(o);
}
// Low 13 mantissa bits (the part tf32 hardware truncation discards)
__device__ __forceinline__ float lo_part(float x) {
    return x - __uint_as_float(__float_as_uint(x) & 0xFFFFE000u);
}
__device__ __forceinline__ float sigf(float x) { return 1.f / (1.f + expf(-x)); }

#define MMA(d, a, b0, b1) \
    asm("mma.sync.aligned.m16n8k8.row.col.f32.tf32.tf32.f32 " \
        "{%0,%1,%2,%3}, {%4,%5,%6,%7}, {%8,%9}, {%0,%1,%2,%3};" \
        : "+f"(d[0]), "+f"(d[1]), "+f"(d[2]), "+f"(d[3]) \
        : "r"(a.x), "r"(a.y), "r"(a.z), "r"(a.w), "r"(b0), "r"(b1))

// Full-precision update for TWO A-slabs sharing one B fragment pair:
// 1x LDS-derived b + 1x lo_part feeds 6 MMAs.
#define MMA3x2(d0, d1, Ah0, Al0, Ah1, Al1, bv0, bv1) do {      \
    u32 _b0 = __float_as_uint(bv0), _b1 = __float_as_uint(bv1);\
    u32 _l0 = __float_as_uint(lo_part(bv0));                   \
    u32 _l1 = __float_as_uint(lo_part(bv1));                   \
    MMA(d0, Ah0, _b0, _b1);                                    \
    MMA(d0, Al0, _b0, _b1);                                    \
    MMA(d0, Ah0, _l0, _l1);                                    \
    MMA(d1, Ah1, _b0, _b1);                                    \
    MMA(d1, Al1, _b0, _b1);                                    \
    MMA(d1, Ah1, _l0, _l1);                                    \
} while (0)

__device__ __forceinline__ void fma4(float4 &a, float w, const float4 &v) {
    a.x = fmaf(w, v.x, a.x); a.y = fmaf(w, v.y, a.y);
    a.z = fmaf(w, v.z, a.z); a.w = fmaf(w, v.w, a.w);
}

// ---------------------------------------------------------------------------
// Prep: build fragment-ordered hi/lo tf32 weights
// ---------------------------------------------------------------------------
__global__ void prep_kernel(const float* __restrict__ wc, const float* __restrict__ wf,
                            const float* __restrict__ wg, const float* __restrict__ wr,
                            const float* __restrict__ ws) {
    int idx = blockIdx.x * blockDim.x + threadIdx.x;
    const int PER = P1N + P2N + P3N;
    if (idx >= NBLK * PER) return;
    int lyr = idx / PER;
    int e = idx % PER;
    float w; float *dh, *dl;
    if (e < P1N) {
        int slab = e >> 11, kt = (e >> 7) & 15, lane = (e >> 2) & 31, r = e & 3;
        int row = slab * 16 + (lane >> 2) + 8 * (r & 1);
        int k = kt * 8 + (lane & 3) + 4 * (r >> 1);
        w = (k < 64) ? wc[(((size_t)lyr * 64 + row) * 64 + k) * 2]
                     : wc[(((size_t)lyr * 64 + row) * 64 + (k - 64)) * 2 + 1];
        dh = g_p1h + (size_t)lyr * P1N + e;
        dl = g_p1l + (size_t)lyr * P1N + e;
    } else if (e < P1N + P2N) {
        int e2 = e - P1N;
        int slab = e2 >> 10, kt = (e2 >> 7) & 7, lane = (e2 >> 2) & 31, r = e2 & 3;
        int ch = slab * 8 + (lane >> 2);
        int k = kt * 8 + (lane & 3) + 4 * (r >> 1);
        w = ((r & 1) == 0) ? wf[((size_t)lyr * 64 + ch) * 64 + k]
                           : wg[((size_t)lyr * 64 + ch) * 64 + k];
        dh = g_p2h + (size_t)lyr * P2N + e2;
        dl = g_p2l + (size_t)lyr * P2N + e2;
    } else {
        int e3 = e - P1N - P2N;
        int slab = e3 >> 10, kt = (e3 >> 7) & 7, lane = (e3 >> 2) & 31, r = e3 & 3;
        int cp = slab * 16 + (lane >> 2) + 8 * (r & 1);
        int k = kt * 8 + (lane & 3) + 4 * (r >> 1);
        w = (cp < 64) ? wr[((size_t)lyr * 64 + cp) * 64 + k]
                      : ws[((size_t)lyr * 128 + (cp - 64)) * 64 + k];
        dh = g_p3h + (size_t)lyr * P3N + e3;
        dl = g_p3l + (size_t)lyr * P3N + e3;
    }
    float hi = tf32r(w);
    *dh = hi;
    *dl = tf32r(w - hi);
}

// ---------------------------------------------------------------------------
// Kernel 1: input 1x1 conv
// ---------------------------------------------------------------------------
__global__ void input_kernel(const float* __restrict__ x,
                             const float* __restrict__ w_in,
                             const float* __restrict__ b_in) {
    int idx = blockIdx.x * blockDim.x + threadIdx.x;
    int t = idx & (T - 1);
    int r = (idx >> 15) & (R - 1);
    int b = idx >> 21;
    g_h[0][idx] = fmaf(__ldg(&w_in[r]), __ldg(&x[b * T + t]), __ldg(&b_in[r]));
}

// ---------------------------------------------------------------------------
// Kernel 2: fused WaveNet block on tensor cores.
// Warp mapping per phase: (slab-PAIR, nb-half, nt-half) so one B fragment
// feeds MMAs for 2 A-slabs (halves B LDS + lo_part work).
// ---------------------------------------------------------------------------
__global__ void __launch_bounds__(256, 2) block_kernel(
    const float* __restrict__ h_in, float* __restrict__ h_out,
    const uint4* __restrict__ p1h, const uint4* __restrict__ p1l, const float* __restrict__ bc,
    const uint4* __restrict__ p2h, const uint4* __restrict__ p2l, const float* __restrict__ bf,
    const float* __restrict__ bg,
    const uint4* __restrict__ p3h, const uint4* __restrict__ p3l, const float* __restrict__ br,
    const float* __restrict__ bs,
    int d, int first)
{
    extern __shared__ float sm[];
    float* s_hn = sm;                 // [64][AST] fp32 h(t)
    float* s_hp = sm + 64 * AST;      // [64][AST] fp32 h(t-d); reused as 'a'
    float* s_z  = sm + 2 * 64 * AST;  // [64][AST] fp32 z

    const int b = blockIdx.y, t0 = blockIdx.x * TT;
    const int tid = threadIdx.x, wp = tid >> 5, l = tid & 31;
    const int lk = l & 3, ln = l >> 2;       // B-frag k row / n col within tile
    const float* hbase = h_in + (size_t)b * R * T;

    // ---- Phase 0: load activation tiles (exact fp32) ----
    for (int f = tid; f < R * 32; f += 256) {
        int row = f >> 5, c4 = f & 31;
        float4 v = ((const float4*)(hbase + (size_t)row * T + t0))[c4];
        *(float4*)(s_hn + row * AST + c4 * 4) = v;
    }
    if ((d & 3) == 0) {
        const int dq = d >> 2;
        for (int f = tid; f < R * 32; f += 256) {
            int row = f >> 5, c4 = f & 31;
            int tq = (t0 >> 2) + c4 - dq;
            float4 v = (tq >= 0) ? ((const float4*)(hbase + (size_t)row * T))[tq]
                                 : make_float4(0.f, 0.f, 0.f, 0.f);
            *(float4*)(s_hp + row * AST + c4 * 4) = v;
        }
    } else {
        for (int idx = tid; idx < R * TT; idx += 256) {
            int row = idx >> 7, col = idx & 127;
            int t = t0 + col - d;
            s_hp[row * AST + col] = (t >= 0) ? hbase[(size_t)row * T + t] : 0.f;
        }
    }
    __syncthreads();

    // ---- Phase 1: z = Wc x [hp; hn]  (M=64 = 2 slab-pairs, K=128, 16 kt) ----
    {
        const int sp = wp >> 2;              // slab pair (slabs 2sp, 2sp+1)
        const int rem = wp & 3;
        const int nb = (rem >> 1) * 64;      // n half (cols 0-63 / 64-127)
        const int nh = rem & 1;              // nt half (4 nt each)
        const int s0 = 2 * sp, s1 = 2 * sp + 1;
        float acc0[4][4], acc1[4][4];
        #pragma unroll
        for (int j = 0; j < 4; j++) {
            acc0[j][0] = acc0[j][1] = acc0[j][2] = acc0[j][3] = 0.f;
            acc1[j][0] = acc1[j][1] = acc1[j][2] = acc1[j][3] = 0.f;
        }
        #pragma unroll 4
        for (int kt = 0; kt < 16; kt++) {
            uint4 Ah0 = __ldg(&p1h[(s0 * 16 + kt) * 32 + l]);
            uint4 Al0 = __ldg(&p1l[(s0 * 16 + kt) * 32 + l]);
            uint4 Ah1 = __ldg(&p1h[(s1 * 16 + kt) * 32 + l]);
            uint4 Al1 = __ldg(&p1l[(s1 * 16 + kt) * 32 + l]);
            const float* bp = ((kt < 8) ? s_hp + kt * 8 * AST
                                        : s_hn + (kt - 8) * 8 * AST)
                              + lk * AST + ln + nb + nh * 32;
            #pragma unroll
            for (int j = 0; j < 4; j++) {
                float bv0 = bp[j * 8];
                float bv1 = bp[4 * AST + j * 8];
                MMA3x2(acc0[j], acc1[j], Ah0, Al0, Ah1, Al1, bv0, bv1);
            }
        }
        #pragma unroll
        for (int s = 0; s < 2; s++) {
            float (*ac)[4] = s ? acc1 : acc0;
            int r0 = (2 * sp + s) * 16 + ln;
            float bv0 = __ldg(bc + r0), bv1 = __ldg(bc + r0 + 8);
            #pragma unroll
            for (int j = 0; j < 4; j++) {
                int c0 = nb + (nh * 4 + j) * 8 + 2 * lk;
                float2 v0 = { ac[j][0] + bv0, ac[j][1] + bv0 };
                float2 v1 = { ac[j][2] + bv1, ac[j][3] + bv1 };
                *(float2*)(s_z + r0 * AST + c0) = v0;
                *(float2*)(s_z + (r0 + 8) * AST + c0) = v1;
            }
        }
    }
    __syncthreads();

    // ---- Phase 2: a = tanh(Wf z) * sigmoid(Wg z)  (8 slabs = 4 pairs, K=64) ----
    #pragma unroll
    for (int ui = 0; ui < 2; ui++) {
        int u = wp + ui * 8;                 // 0..15
        int sp = u >> 2, rem = u & 3;
        int nb = (rem >> 1) * 64, nh = rem & 1;
        int s0 = 2 * sp, s1 = 2 * sp + 1;
        float acc0[4][4], acc1[4][4];
        #pragma unroll
        for (int j = 0; j < 4; j++) {
            acc0[j][0] = acc0[j][1] = acc0[j][2] = acc0[j][3] = 0.f;
            acc1[j][0] = acc1[j][1] = acc1[j][2] = acc1[j][3] = 0.f;
        }
        #pragma unroll 2
        for (int kt = 0; kt < 8; kt++) {
            uint4 Ah0 = __ldg(&p2h[(s0 * 8 + kt) * 32 + l]);
            uint4 Al0 = __ldg(&p2l[(s0 * 8 + kt) * 32 + l]);
            uint4 Ah1 = __ldg(&p2h[(s1 * 8 + kt) * 32 + l]);
            uint4 Al1 = __ldg(&p2l[(s1 * 8 + kt) * 32 + l]);
            const float* bp = s_z + (kt * 8 + lk) * AST + ln + nb + nh * 32;
            #pragma unroll
            for (int j = 0; j < 4; j++) {
                float bv0 = bp[j * 8];
                float bv1 = bp[4 * AST + j * 8];
                MMA3x2(acc0[j], acc1[j], Ah0, Al0, Ah1, Al1, bv0, bv1);
            }
        }
        #pragma unroll
        for (int s = 0; s < 2; s++) {
            float (*ac)[4] = s ? acc1 : acc0;
            int ch = (2 * sp + s) * 8 + ln;
            float bfv = __ldg(bf + ch), bgv = __ldg(bg + ch);
            #pragma unroll
            for (int j = 0; j < 4; j++) {
                int c0 = nb + (nh * 4 + j) * 8 + 2 * lk;
                float a0 = tanhf(ac[j][0] + bfv) * sigf(ac[j][2] + bgv);
                float a1 = tanhf(ac[j][1] + bfv) * sigf(ac[j][3] + bgv);
                float2 v = { a0, a1 };
                *(float2*)(s_hp + ch * AST + c0) = v;   // a overwrites hp
            }
        }
    }
    __syncthreads();

    // ---- Phase 3: res (rows 0-63) + skip (rows 64-191)  (12 slabs = 6 pairs) ----
    {
        float* hdst = h_out + (size_t)b * R * T + t0;
        const float* hsrc = h_in + (size_t)b * R * T + t0;
        float* skp = g_skip + (size_t)b * S * T + t0;
        #pragma unroll
        for (int ui = 0; ui < 3; ui++) {
            int u = wp + ui * 8;             // 0..23
            int sp = u >> 2, rem = u & 3;
            int nb = (rem >> 1) * 64, nh = rem & 1;
            int s0 = 2 * sp, s1 = 2 * sp + 1;
            float acc0[4][4], acc1[4][4];
            #pragma unroll
            for (int j = 0; j < 4; j++) {
                acc0[j][0] = acc0[j][1] = acc0[j][2] = acc0[j][3] = 0.f;
                acc1[j][0] = acc1[j][1] = acc1[j][2] = acc1[j][3] = 0.f;
            }
            #pragma unroll 2
            for (int kt = 0; kt < 8; kt++) {
                uint4 Ah0 = __ldg(&p3h[(s0 * 8 + kt) * 32 + l]);
                uint4 Al0 = __ldg(&p3l[(s0 * 8 + kt) * 32 + l]);
                uint4 Ah1 = __ldg(&p3h[(s1 * 8 + kt) * 32 + l]);
                uint4 Al1 = __ldg(&p3l[(s1 * 8 + kt) * 32 + l]);
                const float* bp = s_hp + (kt * 8 + lk) * AST + ln + nb + nh * 32;
                #pragma unroll
                for (int j = 0; j < 4; j++) {
                    float bv0 = bp[j * 8];
                    float bv1 = bp[4 * AST + j * 8];
                    MMA3x2(acc0[j], acc1[j], Ah0, Al0, Ah1, Al1, bv0, bv1);
                }
            }
            #pragma unroll
            for (int s = 0; s < 2; s++) {
                float (*ac)[4] = s ? acc1 : acc0;
                int r0 = (2 * sp + s) * 16 + ln;
                if (r0 < 64) {
                    float br0 = __ldg(br + r0), br1 = __ldg(br + r0 + 8);
                    #pragma unroll
                    for (int j = 0; j < 4; j++) {
                        int c0 = nb + (nh * 4 + j) * 8 + 2 * lk;
                        float2 h0 = *(const float2*)(hsrc + (size_t)r0 * T + c0);
                        float2 h1 = *(const float2*)(hsrc + (size_t)(r0 + 8) * T + c0);
                        float2 v0 = { ac[j][0] + br0 + h0.x, ac[j][1] + br0 + h0.y };
                        float2 v1 = { ac[j][2] + br1 + h1.x, ac[j][3] + br1 + h1.y };
                        *(float2*)(hdst + (size_t)r0 * T + c0) = v0;
                        *(float2*)(hdst + (size_t)(r0 + 8) * T + c0) = v1;
                    }
                } else {
                    int sk0 = r0 - 64;
                    float bs0 = __ldg(bs + sk0), bs1 = __ldg(bs + sk0 + 8);
                    #pragma unroll
                    for (int j = 0; j < 4; j++) {
                        int c0 = nb + (nh * 4 + j) * 8 + 2 * lk;
                        float2* g0 = (float2*)(skp + (size_t)sk0 * T + c0);
                        float2* g1 = (float2*)(skp + (size_t)(sk0 + 8) * T + c0);
                        float2 v0 = { ac[j][0] + bs0, ac[j][1] + bs0 };
                        float2 v1 = { ac[j][2] + bs1, ac[j][3] + bs1 };
                        if (!first) {
                            float2 o0 = *g0, o1 = *g1;
                            v0.x += o0.x; v0.y += o0.y; v1.x += o1.x; v1.y += o1.y;
                        }
                        *g0 = v0; *g1 = v1;
                    }
                }
            }
        }
    }
}

// ---------------------------------------------------------------------------
// Kernel 3: head (fp32)
// ---------------------------------------------------------------------------
__global__ void __launch_bounds__(256) head_kernel(
    const float* __restrict__ w1, const float* __restrict__ b1,
    const float* __restrict__ w2, const float* __restrict__ b2,
    float* __restrict__ out)
{
    extern __shared__ float smem[];
    float* sk   = smem;
    float* part = smem + S * TT;

    const int b = blockIdx.y, t0 = blockIdx.x * TT;
    const int tid = threadIdx.x, wp = tid >> 5, l = tid & 31;
    const float* skg = g_skip + (size_t)b * S * T + t0;

    for (int f = tid; f < S * TT / 4; f += 256) {
        int row = f >> 5, col = f & 31;
        float4 v = ((const float4*)(skg + (size_t)row * T))[col];
        v.x = fmaxf(v.x, 0.f); v.y = fmaxf(v.y, 0.f);
        v.z = fmaxf(v.z, 0.f); v.w = fmaxf(v.w, 0.f);
        ((float4*)sk)[f] = v;
    }
    __syncthreads();

    const float4* sk4 = (const float4*)sk;
    float4 po = {0.f, 0.f, 0.f, 0.f};
    for (int s2 = wp * 16; s2 < wp * 16 + 16; s2++) {
        float4 u = {0.f, 0.f, 0.f, 0.f};
        const float* wrow = w1 + (s2 << 7);
        #pragma unroll 8
        for (int s1 = 0; s1 < S; s1++)
            fma4(u, __ldg(wrow + s1), sk4[(s1 << 5) + l]);
        float bb = __ldg(b1 + s2);
        u.x = fmaxf(u.x + bb, 0.f); u.y = fmaxf(u.y + bb, 0.f);
        u.z = fmaxf(u.z + bb, 0.f); u.w = fmaxf(u.w + bb, 0.f);
        fma4(po, __ldg(w2 + s2), u);
    }
    ((float4*)(part + wp * TT))[l] = po;
    __syncthreads();

    if (tid < TT) {
        float acc = __ldg(b2);
        #pragma unroll
        for (int ww = 0; ww < 8; ww++) acc += part[ww * TT + tid];
        out[(size_t)b * T + t0 + tid] = acc;
    }
}

// ---------------------------------------------------------------------------
extern "C" void kernel_launch(void* const* d_in, const int* in_sizes, int n_in,
                              void* d_out, int out_size) {
    const float* x        = (const float*)d_in[0];
    const float* w_in     = (const float*)d_in[1];
    const float* b_in     = (const float*)d_in[2];
    const float* w_causal = (const float*)d_in[3];
    const float* b_causal = (const float*)d_in[4];
    const float* w_filter = (const float*)d_in[5];
    const float* b_filter = (const float*)d_in[6];
    const float* w_gate   = (const float*)d_in[7];
    const float* b_gate   = (const float*)d_in[8];
    const float* w_res    = (const float*)d_in[9];
    const float* b_res    = (const float*)d_in[10];
    const float* w_skip   = (const float*)d_in[11];
    const float* b_skip   = (const float*)d_in[12];
    const float* w_out1   = (const float*)d_in[13];
    const float* b_out1   = (const float*)d_in[14];
    const float* w_out2   = (const float*)d_in[15];
    const float* b_out2   = (const float*)d_in[16];
    float* out = (float*)d_out;

    const int blk_smem  = 3 * 64 * AST * 4;          // ~102 KB
    const int head_smem = (S * TT + 8 * TT) * 4;     // 68 KB
    cudaFuncSetAttribute(block_kernel, cudaFuncAttributeMaxDynamicSharedMemorySize, blk_smem);
    cudaFuncSetAttribute(head_kernel,  cudaFuncAttributeMaxDynamicSharedMemorySize, head_smem);

    float *hbuf0, *p1h, *p1l, *p2h, *p2l, *p3h, *p3l;
    cudaGetSymbolAddress((void**)&hbuf0, g_h);
    cudaGetSymbolAddress((void**)&p1h, g_p1h);
    cudaGetSymbolAddress((void**)&p1l, g_p1l);
    cudaGetSymbolAddress((void**)&p2h, g_p2h);
    cudaGetSymbolAddress((void**)&p2l, g_p2l);
    cudaGetSymbolAddress((void**)&p3h, g_p3h);
    cudaGetSymbolAddress((void**)&p3l, g_p3l);
    float* hbuf[2] = { hbuf0, hbuf0 + (size_t)BB * R * T };

    const int pre_total = NBLK * (P1N + P2N + P3N);
    prep_kernel<<<(pre_total + 255) / 256, 256>>>(w_causal, w_filter, w_gate, w_res, w_skip);

    input_kernel<<<BB * R * T / 256, 256>>>(x, w_in, b_in);

    dim3 grid(T / TT, BB);
    for (int i = 0; i < NBLK; i++) {
        int d = 1 << (i & 7);
        block_kernel<<<grid, 256, blk_smem>>>(
            hbuf[i & 1], hbuf[(i + 1) & 1],
            (const uint4*)(p1h + (size_t)i * P1N), (const uint4*)(p1l + (size_t)i * P1N),
            b_causal + (size_t)i * R,
            (const uint4*)(p2h + (size_t)i * P2N), (const uint4*)(p2l + (size_t)i * P2N),
            b_filter + (size_t)i * R, b_gate + (size_t)i * R,
            (const uint4*)(p3h + (size_t)i * P3N), (const uint4*)(p3l + (size_t)i * P3N),
            b_res + (size_t)i * R, b_skip + (size_t)i * S,
            d, i == 0 ? 1 : 0);
    }

    head_kernel<<<grid, 256, head_smem>>>(w_out1, b_out1, w_out2, b_out2, out);
}

// round 9
// speedup vs baseline: 1.2205x; 1.2084x over previous
#include <cuda_runtime.h>
#include <cuda_bf16.h>

#define BB 8
#define T 32768
#define R 64
#define S 128
#define NBLK 24
#define TT 128
#define SB 36              // u32 words per timestep row (32 ch-pairs + 4 pad)
#define TNW (128 * SB)     // words per tensor plane (hi or lo) = 4608

typedef unsigned int u32;
typedef unsigned short u16;

__device__ __align__(16) float g_h[2][BB * R * T];   // ping-pong fp32 residual stream
__device__ __align__(16) float g_skip[BB * S * T];   // fp32 skip accumulator

// Fragment-ordered bf16 weights (packed pairs), hi + lo split, built by prep_kernel.
// Q1: conv [M=64,K=128]: 4 slabs x 8 kt x 32 lanes x 4 regs
// Q2: f|g  [M=128,K=64]: 8 slabs x 4 kt (slab rows 0-7 filter, 8-15 gate)
// Q3: r|s  [M=192,K=64]: 12 slabs x 4 kt
#define Q1N 4096
#define Q2N 4096
#define Q3N 6144
__device__ __align__(16) u32 g_q1h[NBLK * Q1N], g_q1l[NBLK * Q1N];
__device__ __align__(16) u32 g_q2h[NBLK * Q2N], g_q2l[NBLK * Q2N];
__device__ __align__(16) u32 g_q3h[NBLK * Q3N], g_q3l[NBLK * Q3N];

__device__ __forceinline__ float sigf(float x) { return 1.f / (1.f + expf(-x)); }

__device__ __forceinline__ void split2(float v, u16 &h, u16 &lo) {
    __nv_bfloat16 bh = __float2bfloat16_rn(v);
    h = __bfloat16_as_ushort(bh);
    lo = __bfloat16_as_ushort(__float2bfloat16_rn(v - __bfloat162float(bh)));
}

// store fp32 value as bf16 hi/lo into packed-u16 tensor planes at (channel r, time c)
__device__ __forceinline__ void store_split(u32* hiBase, int c, int r, float v) {
    u16 h, lo;
    split2(v, h, lo);
    ((u16*)hiBase)[c * (2 * SB) + r] = h;
    ((u16*)(hiBase + TNW))[c * (2 * SB) + r] = lo;
}

#define MMAB(d, a, b0, b1) \
    asm("mma.sync.aligned.m16n8k16.row.col.f32.bf16.bf16.f32 " \
        "{%0,%1,%2,%3}, {%4,%5,%6,%7}, {%8,%9}, {%0,%1,%2,%3};" \
        : "+f"(d[0]), "+f"(d[1]), "+f"(d[2]), "+f"(d[3]) \
        : "r"(a.x), "r"(a.y), "r"(a.z), "r"(a.w), "r"(b0), "r"(b1))

// 3-product bf16 scheme for two A-slabs sharing one B fragment set (6 MMAs)
#define MMA3x2B(d0, d1, Ah0, Al0, Ah1, Al1, bh0, bh1, bl0, bl1) do { \
    MMAB(d0, Ah0, bh0, bh1);                                         \
    MMAB(d0, Ah0, bl0, bl1);                                         \
    MMAB(d0, Al0, bh0, bh1);                                         \
    MMAB(d1, Ah1, bh0, bh1);                                         \
    MMAB(d1, Ah1, bl0, bl1);                                         \
    MMAB(d1, Al1, bh0, bh1);                                         \
} while (0)

__device__ __forceinline__ void fma4(float4 &a, float w, const float4 &v) {
    a.x = fmaf(w, v.x, a.x); a.y = fmaf(w, v.y, a.y);
    a.z = fmaf(w, v.z, a.z); a.w = fmaf(w, v.w, a.w);
}

// ---------------------------------------------------------------------------
// Prep: fragment-ordered bf16 hi/lo weight pairs (once per launch)
// ---------------------------------------------------------------------------
__global__ void prep_kernel(const float* __restrict__ wc, const float* __restrict__ wf,
                            const float* __restrict__ wg, const float* __restrict__ wr,
                            const float* __restrict__ ws) {
    int idx = blockIdx.x * blockDim.x + threadIdx.x;
    const int PER = Q1N + Q2N + Q3N;
    if (idx >= NBLK * PER) return;
    int lyr = idx / PER;
    int e = idx % PER;
    float w0, w1; u32 *dh, *dl;
    if (e < Q1N) {
        int slab = e >> 10, kt = (e >> 7) & 7, lane = (e >> 2) & 31, r = e & 3;
        int row = slab * 16 + (lane >> 2) + 8 * (r & 1);
        int k = kt * 16 + 2 * (lane & 3) + 8 * (r >> 1);
        #define WC(kk) ((kk) < 64 ? wc[(((size_t)lyr * 64 + row) * 64 + (kk)) * 2] \
                                  : wc[(((size_t)lyr * 64 + row) * 64 + (kk) - 64) * 2 + 1])
        w0 = WC(k); w1 = WC(k + 1);
        #undef WC
        dh = g_q1h + (size_t)lyr * Q1N + e;
        dl = g_q1l + (size_t)lyr * Q1N + e;
    } else if (e < Q1N + Q2N) {
        int e2 = e - Q1N;
        int slab = e2 >> 9, kt = (e2 >> 7) & 3, lane = (e2 >> 2) & 31, r = e2 & 3;
        int row = (lane >> 2) + 8 * (r & 1);           // 0..15 within tile
        int ch = slab * 8 + (row & 7);
        int k = kt * 16 + 2 * (lane & 3) + 8 * (r >> 1);
        const float* src = (row < 8) ? wf : wg;
        w0 = src[((size_t)lyr * 64 + ch) * 64 + k];
        w1 = src[((size_t)lyr * 64 + ch) * 64 + k + 1];
        dh = g_q2h + (size_t)lyr * Q2N + e2;
        dl = g_q2l + (size_t)lyr * Q2N + e2;
    } else {
        int e3 = e - Q1N - Q2N;
        int slab = e3 >> 9, kt = (e3 >> 7) & 3, lane = (e3 >> 2) & 31, r = e3 & 3;
        int grow = slab * 16 + (lane >> 2) + 8 * (r & 1);  // 0..191
        int k = kt * 16 + 2 * (lane & 3) + 8 * (r >> 1);
        if (grow < 64) {
            w0 = wr[((size_t)lyr * 64 + grow) * 64 + k];
            w1 = wr[((size_t)lyr * 64 + grow) * 64 + k + 1];
        } else {
            w0 = ws[((size_t)lyr * 128 + grow - 64) * 64 + k];
            w1 = ws[((size_t)lyr * 128 + grow - 64) * 64 + k + 1];
        }
        dh = g_q3h + (size_t)lyr * Q3N + e3;
        dl = g_q3l + (size_t)lyr * Q3N + e3;
    }
    u16 h0, l0, h1, l1;
    split2(w0, h0, l0);
    split2(w1, h1, l1);
    *dh = ((u32)h1 << 16) | h0;
    *dl = ((u32)l1 << 16) | l0;
}

// ---------------------------------------------------------------------------
// Kernel 1: input 1x1 conv
// ---------------------------------------------------------------------------
__global__ void input_kernel(const float* __restrict__ x,
                             const float* __restrict__ w_in,
                             const float* __restrict__ b_in) {
    int idx = blockIdx.x * blockDim.x + threadIdx.x;
    int t = idx & (T - 1);
    int r = (idx >> 15) & (R - 1);
    int b = idx >> 21;
    g_h[0][idx] = fmaf(__ldg(&w_in[r]), __ldg(&x[b * T + t]), __ldg(&b_in[r]));
}

// ---------------------------------------------------------------------------
// Kernel 2: fused WaveNet block, bf16 m16n8k16 3-product (double-double).
// smem tensors: packed channel-pair u32, time-major [t][SB], hi plane + lo plane.
// ---------------------------------------------------------------------------
__global__ void __launch_bounds__(256, 2) block_kernel(
    const float* __restrict__ h_in, float* __restrict__ h_out,
    const uint4* __restrict__ q1h, const uint4* __restrict__ q1l, const float* __restrict__ bc,
    const uint4* __restrict__ q2h, const uint4* __restrict__ q2l, const float* __restrict__ bf,
    const float* __restrict__ bg,
    const uint4* __restrict__ q3h, const uint4* __restrict__ q3l, const float* __restrict__ br,
    const float* __restrict__ bs,
    int d, int first)
{
    extern __shared__ u32 sm32[];
    u32* s_hp = sm32;               // h(t-d) hi; lo at +TNW   (reused as 'a' later)
    u32* s_hn = sm32 + 2 * TNW;     // h(t)   hi; lo at +TNW
    u32* s_z  = sm32 + 4 * TNW;     // z      hi; lo at +TNW

    const int b = blockIdx.y, t0 = blockIdx.x * TT;
    const int tid = threadIdx.x, wp = tid >> 5, l = tid & 31;
    const int lk = l & 3, ln = l >> 2;
    const float* hbase = h_in + (size_t)b * R * T;

    // ---- Phase 0: load fp32 h, bf16-split into packed smem planes ----
    for (int idx = tid; idx < 1024; idx += 256) {
        int rp = idx & 31, c4 = idx >> 5;   // ch-pair, float4 col
        float4 v0 = ((const float4*)(hbase + (size_t)(2 * rp) * T + t0))[c4];
        float4 v1 = ((const float4*)(hbase + (size_t)(2 * rp + 1) * T + t0))[c4];
        const float* e0 = (const float*)&v0;
        const float* e1 = (const float*)&v1;
        #pragma unroll
        for (int i = 0; i < 4; i++) {
            u16 h0, l0, h1, l1;
            split2(e0[i], h0, l0);
            split2(e1[i], h1, l1);
            s_hn[(c4 * 4 + i) * SB + rp] = ((u32)h1 << 16) | h0;
            s_hn[(c4 * 4 + i) * SB + rp + TNW] = ((u32)l1 << 16) | l0;
        }
    }
    if ((d & 3) == 0) {
        const int dq = d >> 2;
        for (int idx = tid; idx < 1024; idx += 256) {
            int rp = idx & 31, c4 = idx >> 5;
            int tq = (t0 >> 2) + c4 - dq;
            float4 v0, v1;
            if (tq >= 0) {
                v0 = ((const float4*)(hbase + (size_t)(2 * rp) * T))[tq];
                v1 = ((const float4*)(hbase + (size_t)(2 * rp + 1) * T))[tq];
            } else {
                v0 = make_float4(0.f, 0.f, 0.f, 0.f);
                v1 = v0;
            }
            const float* e0 = (const float*)&v0;
            const float* e1 = (const float*)&v1;
            #pragma unroll
            for (int i = 0; i < 4; i++) {
                u16 h0, l0, h1, l1;
                split2(e0[i], h0, l0);
                split2(e1[i], h1, l1);
                s_hp[(c4 * 4 + i) * SB + rp] = ((u32)h1 << 16) | h0;
                s_hp[(c4 * 4 + i) * SB + rp + TNW] = ((u32)l1 << 16) | l0;
            }
        }
    } else {
        for (int idx = tid; idx < 4096; idx += 256) {
            int rp = idx & 31, t = idx >> 5;
            int ts = t0 + t - d;
            float a0 = 0.f, a1 = 0.f;
            if (ts >= 0) {
                a0 = hbase[(size_t)(2 * rp) * T + ts];
                a1 = hbase[(size_t)(2 * rp + 1) * T + ts];
            }
            u16 h0, l0, h1, l1;
            split2(a0, h0, l0);
            split2(a1, h1, l1);
            s_hp[t * SB + rp] = ((u32)h1 << 16) | h0;
            s_hp[t * SB + rp + TNW] = ((u32)l1 << 16) | l0;
        }
    }
    __syncthreads();

    // ---- Phase 1: z = Wc x [hp; hn]  (M=64, K=128 -> 8 ktiles) ----
    {
        const int sp = wp >> 2, rem = wp & 3;
        const int cb = (rem >> 1) * 64 + (rem & 1) * 32;   // 32-col window
        const int s0 = 2 * sp, s1 = s0 + 1;
        float acc0[4][4], acc1[4][4];
        #pragma unroll
        for (int j = 0; j < 4; j++) {
            acc0[j][0] = acc0[j][1] = acc0[j][2] = acc0[j][3] = 0.f;
            acc1[j][0] = acc1[j][1] = acc1[j][2] = acc1[j][3] = 0.f;
        }
        #pragma unroll 2
        for (int kt = 0; kt < 8; kt++) {
            uint4 Ah0 = __ldg(&q1h[(s0 * 8 + kt) * 32 + l]);
            uint4 Al0 = __ldg(&q1l[(s0 * 8 + kt) * 32 + l]);
            uint4 Ah1 = __ldg(&q1h[(s1 * 8 + kt) * 32 + l]);
            uint4 Al1 = __ldg(&q1l[(s1 * 8 + kt) * 32 + l]);
            const u32* bh = ((kt < 4) ? s_hp : s_hn) + (kt & 3) * 8 + lk + (cb + ln) * SB;
            #pragma unroll
            for (int j = 0; j < 4; j++) {
                u32 bh0 = bh[j * 8 * SB], bh1 = bh[j * 8 * SB + 4];
                u32 bl0 = bh[j * 8 * SB + TNW], bl1 = bh[j * 8 * SB + TNW + 4];
                MMA3x2B(acc0[j], acc1[j], Ah0, Al0, Ah1, Al1, bh0, bh1, bl0, bl1);
            }
        }
        #pragma unroll
        for (int s = 0; s < 2; s++) {
            float (*ac)[4] = s ? acc1 : acc0;
            int r0 = (2 * sp + s) * 16 + ln;
            float bv0 = __ldg(bc + r0), bv1 = __ldg(bc + r0 + 8);
            #pragma unroll
            for (int j = 0; j < 4; j++) {
                int c0 = cb + j * 8 + 2 * lk;
                store_split(s_z, c0,     r0,     ac[j][0] + bv0);
                store_split(s_z, c0 + 1, r0,     ac[j][1] + bv0);
                store_split(s_z, c0,     r0 + 8, ac[j][2] + bv1);
                store_split(s_z, c0 + 1, r0 + 8, ac[j][3] + bv1);
            }
        }
    }
    __syncthreads();

    // ---- Phase 2: a = tanh(Wf z + bf) * sigmoid(Wg z + bg)  (M=128, K=64) ----
    // a overwrites s_hp (phase 1 fully done reading it).
    #pragma unroll
    for (int ui = 0; ui < 2; ui++) {
        int u = wp + ui * 8;
        int sp = u >> 2, rem = u & 3;
        int cb = (rem >> 1) * 64 + (rem & 1) * 32;
        int s0 = 2 * sp, s1 = s0 + 1;
        float acc0[4][4], acc1[4][4];
        #pragma unroll
        for (int j = 0; j < 4; j++) {
            acc0[j][0] = acc0[j][1] = acc0[j][2] = acc0[j][3] = 0.f;
            acc1[j][0] = acc1[j][1] = acc1[j][2] = acc1[j][3] = 0.f;
        }
        #pragma unroll
        for (int kt = 0; kt < 4; kt++) {
            uint4 Ah0 = __ldg(&q2h[(s0 * 4 + kt) * 32 + l]);
            uint4 Al0 = __ldg(&q2l[(s0 * 4 + kt) * 32 + l]);
            uint4 Ah1 = __ldg(&q2h[(s1 * 4 + kt) * 32 + l]);
            uint4 Al1 = __ldg(&q2l[(s1 * 4 + kt) * 32 + l]);
            const u32* bh = s_z + kt * 8 + lk + (cb + ln) * SB;
            #pragma unroll
            for (int j = 0; j < 4; j++) {
                u32 bh0 = bh[j * 8 * SB], bh1 = bh[j * 8 * SB + 4];
                u32 bl0 = bh[j * 8 * SB + TNW], bl1 = bh[j * 8 * SB + TNW + 4];
                MMA3x2B(acc0[j], acc1[j], Ah0, Al0, Ah1, Al1, bh0, bh1, bl0, bl1);
            }
        }
        #pragma unroll
        for (int s = 0; s < 2; s++) {
            float (*ac)[4] = s ? acc1 : acc0;
            int ch = (2 * sp + s) * 8 + ln;
            float bfv = __ldg(bf + ch), bgv = __ldg(bg + ch);
            #pragma unroll
            for (int j = 0; j < 4; j++) {
                int c0 = cb + j * 8 + 2 * lk;
                float a0 = tanhf(ac[j][0] + bfv) * sigf(ac[j][2] + bgv);
                float a1 = tanhf(ac[j][1] + bfv) * sigf(ac[j][3] + bgv);
                store_split(s_hp, c0,     ch, a0);
                store_split(s_hp, c0 + 1, ch, a1);
            }
        }
    }
    __syncthreads();

    // ---- Phase 3: res (rows 0-63) + skip (rows 64-191)  (M=192, K=64) ----
    {
        float* hdst = h_out + (size_t)b * R * T + t0;
        const float* hsrc = h_in + (size_t)b * R * T + t0;
        float* skp = g_skip + (size_t)b * S * T + t0;
        #pragma unroll
        for (int ui = 0; ui < 3; ui++) {
            int u = wp + ui * 8;
            int sp = u >> 2, rem = u & 3;
            int cb = (rem >> 1) * 64 + (rem & 1) * 32;
            int s0 = 2 * sp, s1 = s0 + 1;
            float acc0[4][4], acc1[4][4];
            #pragma unroll
            for (int j = 0; j < 4; j++) {
                acc0[j][0] = acc0[j][1] = acc0[j][2] = acc0[j][3] = 0.f;
                acc1[j][0] = acc1[j][1] = acc1[j][2] = acc1[j][3] = 0.f;
            }
            #pragma unroll
            for (int kt = 0; kt < 4; kt++) {
                uint4 Ah0 = __ldg(&q3h[(s0 * 4 + kt) * 32 + l]);
                uint4 Al0 = __ldg(&q3l[(s0 * 4 + kt) * 32 + l]);
                uint4 Ah1 = __ldg(&q3h[(s1 * 4 + kt) * 32 + l]);
                uint4 Al1 = __ldg(&q3l[(s1 * 4 + kt) * 32 + l]);
                const u32* bh = s_hp + kt * 8 + lk + (cb + ln) * SB;
                #pragma unroll
                for (int j = 0; j < 4; j++) {
                    u32 bh0 = bh[j * 8 * SB], bh1 = bh[j * 8 * SB + 4];
                    u32 bl0 = bh[j * 8 * SB + TNW], bl1 = bh[j * 8 * SB + TNW + 4];
                    MMA3x2B(acc0[j], acc1[j], Ah0, Al0, Ah1, Al1, bh0, bh1, bl0, bl1);
                }
            }
            #pragma unroll
            for (int s = 0; s < 2; s++) {
                float (*ac)[4] = s ? acc1 : acc0;
                int r0 = (2 * sp + s) * 16 + ln;
                if (r0 < 64) {
                    float br0 = __ldg(br + r0), br1 = __ldg(br + r0 + 8);
                    #pragma unroll
                    for (int j = 0; j < 4; j++) {
                        int c0 = cb + j * 8 + 2 * lk;
                        float2 h0 = *(const float2*)(hsrc + (size_t)r0 * T + c0);
                        float2 h1 = *(const float2*)(hsrc + (size_t)(r0 + 8) * T + c0);
                        float2 v0 = { ac[j][0] + br0 + h0.x, ac[j][1] + br0 + h0.y };
                        float2 v1 = { ac[j][2] + br1 + h1.x, ac[j][3] + br1 + h1.y };
                        *(float2*)(hdst + (size_t)r0 * T + c0) = v0;
                        *(float2*)(hdst + (size_t)(r0 + 8) * T + c0) = v1;
                    }
                } else {
                    int sk0 = r0 - 64;
                    float bs0 = __ldg(bs + sk0), bs1 = __ldg(bs + sk0 + 8);
                    #pragma unroll
                    for (int j = 0; j < 4; j++) {
                        int c0 = cb + j * 8 + 2 * lk;
                        float2* g0 = (float2*)(skp + (size_t)sk0 * T + c0);
                        float2* g1 = (float2*)(skp + (size_t)(sk0 + 8) * T + c0);
                        float2 v0 = { ac[j][0] + bs0, ac[j][1] + bs0 };
                        float2 v1 = { ac[j][2] + bs1, ac[j][3] + bs1 };
                        if (!first) {
                            float2 o0 = *g0, o1 = *g1;
                            v0.x += o0.x; v0.y += o0.y; v1.x += o1.x; v1.y += o1.y;
                        }
                        *g0 = v0; *g1 = v1;
                    }
                }
            }
        }
    }
}

// ---------------------------------------------------------------------------
// Kernel 3: head (fp32)
// ---------------------------------------------------------------------------
__global__ void __launch_bounds__(256) head_kernel(
    const float* __restrict__ w1, const float* __restrict__ b1,
    const float* __restrict__ w2, const float* __restrict__ b2,
    float* __restrict__ out)
{
    extern __shared__ float smem[];
    float* sk   = smem;
    float* part = smem + S * TT;

    const int b = blockIdx.y, t0 = blockIdx.x * TT;
    const int tid = threadIdx.x, wp = tid >> 5, l = tid & 31;
    const float* skg = g_skip + (size_t)b * S * T + t0;

    for (int f = tid; f < S * TT / 4; f += 256) {
        int row = f >> 5, col = f & 31;
        float4 v = ((const float4*)(skg + (size_t)row * T))[col];
        v.x = fmaxf(v.x, 0.f); v.y = fmaxf(v.y, 0.f);
        v.z = fmaxf(v.z, 0.f); v.w = fmaxf(v.w, 0.f);
        ((float4*)sk)[f] = v;
    }
    __syncthreads();

    const float4* sk4 = (const float4*)sk;
    float4 po = {0.f, 0.f, 0.f, 0.f};
    for (int s2 = wp * 16; s2 < wp * 16 + 16; s2++) {
        float4 u = {0.f, 0.f, 0.f, 0.f};
        const float* wrow = w1 + (s2 << 7);
        #pragma unroll 8
        for (int s1 = 0; s1 < S; s1++)
            fma4(u, __ldg(wrow + s1), sk4[(s1 << 5) + l]);
        float bb = __ldg(b1 + s2);
        u.x = fmaxf(u.x + bb, 0.f); u.y = fmaxf(u.y + bb, 0.f);
        u.z = fmaxf(u.z + bb, 0.f); u.w = fmaxf(u.w + bb, 0.f);
        fma4(po, __ldg(w2 + s2), u);
    }
    ((float4*)(part + wp * TT))[l] = po;
    __syncthreads();

    if (tid < TT) {
        float acc = __ldg(b2);
        #pragma unroll
        for (int ww = 0; ww < 8; ww++) acc += part[ww * TT + tid];
        out[(size_t)b * T + t0 + tid] = acc;
    }
}

// ---------------------------------------------------------------------------
extern "C" void kernel_launch(void* const* d_in, const int* in_sizes, int n_in,
                              void* d_out, int out_size) {
    const float* x        = (const float*)d_in[0];
    const float* w_in     = (const float*)d_in[1];
    const float* b_in     = (const float*)d_in[2];
    const float* w_causal = (const float*)d_in[3];
    const float* b_causal = (const float*)d_in[4];
    const float* w_filter = (const float*)d_in[5];
    const float* b_filter = (const float*)d_in[6];
    const float* w_gate   = (const float*)d_in[7];
    const float* b_gate   = (const float*)d_in[8];
    const float* w_res    = (const float*)d_in[9];
    const float* b_res    = (const float*)d_in[10];
    const float* w_skip   = (const float*)d_in[11];
    const float* b_skip   = (const float*)d_in[12];
    const float* w_out1   = (const float*)d_in[13];
    const float* b_out1   = (const float*)d_in[14];
    const float* w_out2   = (const float*)d_in[15];
    const float* b_out2   = (const float*)d_in[16];
    float* out = (float*)d_out;

    const int blk_smem  = 6 * TNW * 4;               // 110,592 B
    const int head_smem = (S * TT + 8 * TT) * 4;     // 68 KB
    cudaFuncSetAttribute(block_kernel, cudaFuncAttributeMaxDynamicSharedMemorySize, blk_smem);
    cudaFuncSetAttribute(head_kernel,  cudaFuncAttributeMaxDynamicSharedMemorySize, head_smem);

    float* hbuf0;
    u32 *q1h, *q1l, *q2h, *q2l, *q3h, *q3l;
    cudaGetSymbolAddress((void**)&hbuf0, g_h);
    cudaGetSymbolAddress((void**)&q1h, g_q1h);
    cudaGetSymbolAddress((void**)&q1l, g_q1l);
    cudaGetSymbolAddress((void**)&q2h, g_q2h);
    cudaGetSymbolAddress((void**)&q2l, g_q2l);
    cudaGetSymbolAddress((void**)&q3h, g_q3h);
    cudaGetSymbolAddress((void**)&q3l, g_q3l);
    float* hbuf[2] = { hbuf0, hbuf0 + (size_t)BB * R * T };

    const int pre_total = NBLK * (Q1N + Q2N + Q3N);
    prep_kernel<<<(pre_total + 255) / 256, 256>>>(w_causal, w_filter, w_gate, w_res, w_skip);

    input_kernel<<<BB * R * T / 256, 256>>>(x, w_in, b_in);

    dim3 grid(T / TT, BB);
    for (int i = 0; i < NBLK; i++) {
        int d = 1 << (i & 7);
        block_kernel<<<grid, 256, blk_smem>>>(
            hbuf[i & 1], hbuf[(i + 1) & 1],
            (const uint4*)(q1h + (size_t)i * Q1N), (const uint4*)(q1l + (size_t)i * Q1N),
            b_causal + (size_t)i * R,
            (const uint4*)(q2h + (size_t)i * Q2N), (const uint4*)(q2l + (size_t)i * Q2N),
            b_filter + (size_t)i * R, b_gate + (size_t)i * R,
            (const uint4*)(q3h + (size_t)i * Q3N), (const uint4*)(q3l + (size_t)i * Q3N),
            b_res + (size_t)i * R, b_skip + (size_t)i * S,
            d, i == 0 ? 1 : 0);
    }

    head_kernel<<<grid, 256, head_smem>>>(w_out1, b_out1, w_out2, b_out2, out);
}